// round 15
// baseline (speedup 1.0000x reference)
#include <cuda_runtime.h>
#include <cuda_fp16.h>
#include <cstdint>

// Energy distance, B=16, N=M=256, D=128. Single launch, single wave.
// fp16x2 SIMD sort (each comparator serves TWO (batch,dim) columns), with the
// 512-element column split across 2 warps: 8 half2/thread, 64 thr/column.
// All bitonic levels in-warp (regs/shfl) except two cross-warp smem events
// (K=512 triangle i^511 and substage j=256). Normalized all-ascending net.
// E*N^2 = sum_k (z_{k+1}-z_k)*d_k^2, d = prefix of +/-1 labels (fp16 LSB).
// Cross-CTA fan-in via device scratch + arrival counter.

#define EB 16
#define EN 256
#define ED 128
#define GX 8            // 16 dims (8 half2 pair-columns) per CTA
#define CSTRIDE 768     // staging words per pair-column (12*63+7=763 max)
#define ESTRIDE 520     // exchange words per pair-column (8*63+7=511 max)
#define FULL_MASK 0xFFFFFFFFu
#define LSB2 0x00010001u

__device__ float g_accum[EB];   // zero-init; reset by last CTA each run
__device__ int   g_cnt[EB];

__device__ __forceinline__ unsigned h2u(__half2 h){ union{__half2 h; unsigned u;} x; x.h=h; return x.u; }
__device__ __forceinline__ __half2 u2h(unsigned u){ union{__half2 h; unsigned u;} x; x.u=u; return x.h; }

__device__ __forceinline__ void colbar(int col) {
    asm volatile("bar.sync %0, 64;" :: "r"(col + 1) : "memory");
}

// Packed ascending compare-exchange (both halves independently).
#define CEP(a,b) { const __half2 lo_=__hmin2((a),(b)), hi_=__hmax2((a),(b)); (a)=lo_; (b)=hi_; }

#define IR_J1   { CEP(v[0],v[1]) CEP(v[2],v[3]) CEP(v[4],v[5]) CEP(v[6],v[7]) }
#define IR_J2   { CEP(v[0],v[2]) CEP(v[1],v[3]) CEP(v[4],v[6]) CEP(v[5],v[7]) }
#define IR_J4   { CEP(v[0],v[4]) CEP(v[1],v[5]) CEP(v[2],v[6]) CEP(v[3],v[7]) }
#define IR_TRI4 { CEP(v[0],v[3]) CEP(v[1],v[2]) CEP(v[4],v[7]) CEP(v[5],v[6]) }
#define IR_TRI8 { CEP(v[0],v[7]) CEP(v[1],v[6]) CEP(v[2],v[5]) CEP(v[3],v[4]) }
#define IR_TAIL { IR_J4 IR_J2 IR_J1 }

// Cross-lane substage via shfl: partner lane^m, same register index.
#define SHS(m, P) { __half2 u_[8]; \
    _Pragma("unroll") for (int r_=0;r_<8;r_++) \
        u_[r_] = u2h(__shfl_xor_sync(FULL_MASK, h2u(v[r_]), (m))); \
    _Pragma("unroll") for (int r_=0;r_<8;r_++) \
        v[r_] = (P) ? __hmin2(v[r_],u_[r_]) : __hmax2(v[r_],u_[r_]); }

// Cross-lane triangle via shfl: partner lane^m, register index reversed.
#define SHT(m, P) { __half2 u_[8]; \
    _Pragma("unroll") for (int r_=0;r_<8;r_++) \
        u_[r_] = u2h(__shfl_xor_sync(FULL_MASK, h2u(v[7-r_]), (m))); \
    _Pragma("unroll") for (int r_=0;r_<8;r_++) \
        v[r_] = (P) ? __hmin2(v[r_],u_[r_]) : __hmax2(v[r_],u_[r_]); }

__global__ __launch_bounds__(512) void ed_kernel(
    const float* __restrict__ x1,
    const float* __restrict__ x2,
    float* __restrict__ out)
{
    __shared__ __align__(16) unsigned stg[8 * CSTRIDE];   // 24 KB staging / event-2 buf
    __shared__ __align__(16) unsigned ebf[8 * ESTRIDE];   // 16.3 KB event-1 buf
    __shared__ unsigned nb[8][66];
    __shared__ unsigned ws[8][2];
    __shared__ float wred[16];

    const int b  = blockIdx.y;
    const int d0 = blockIdx.x << 4;        // 16 dims per CTA = 8 half2 pairs
    const int t  = threadIdx.x;            // 0..511
    const int lane  = t & 31;
    const int col   = t >> 6;              // pair-column 0..7
    const int wc    = (t >> 5) & 1;        // warp within column
    const int tid_c = t & 63;              // thread within column

    // ---- Stage: thread t = (sample s = t>>1, half h = t&1) loads 8 dims of
    //      both inputs, packs dim pairs into half2, labels x1->LSB|1, x2->&~1.
    //      Element i = 8*tid_c + r of pair p at word 12*(i>>3) + (i&7);
    //      x1 elem s at W(s), x2 elem 256+s at W(s)+384.
    {
        const int s = t >> 1;
        const int h = t & 1;
        const size_t off = ((size_t)(b * EN + s)) * ED + d0 + (h << 3);
        const float4 a0 = *(const float4*)(x1 + off);
        const float4 a1 = *(const float4*)(x1 + off + 4);
        const float4 b0 = *(const float4*)(x2 + off);
        const float4 b1 = *(const float4*)(x2 + off + 4);
        const unsigned pa[4] = {
            h2u(__floats2half2_rn(a0.x, a0.y)) | LSB2,
            h2u(__floats2half2_rn(a0.z, a0.w)) | LSB2,
            h2u(__floats2half2_rn(a1.x, a1.y)) | LSB2,
            h2u(__floats2half2_rn(a1.z, a1.w)) | LSB2 };
        const unsigned pb[4] = {
            h2u(__floats2half2_rn(b0.x, b0.y)) & ~LSB2,
            h2u(__floats2half2_rn(b0.z, b0.w)) & ~LSB2,
            h2u(__floats2half2_rn(b1.x, b1.y)) & ~LSB2,
            h2u(__floats2half2_rn(b1.z, b1.w)) & ~LSB2 };
        const int W = 12 * (s >> 3) + (s & 7);
        #pragma unroll
        for (int q = 0; q < 4; q++) {
            unsigned* cb = stg + ((h << 2) + q) * CSTRIDE;
            cb[W]       = pa[q];
            cb[W + 384] = pb[q];
        }
    }
    __syncthreads();

    unsigned* cstg = stg + col * CSTRIDE;
    unsigned* ceb  = ebf + col * ESTRIDE;

    __half2 v[8];
    {
        const int base = 12 * tid_c;
        const uint4 q0 = *(const uint4*)(cstg + base);
        const uint4 q1 = *(const uint4*)(cstg + base + 4);
        v[0]=u2h(q0.x); v[1]=u2h(q0.y); v[2]=u2h(q0.z); v[3]=u2h(q0.w);
        v[4]=u2h(q1.x); v[5]=u2h(q1.y); v[6]=u2h(q1.z); v[7]=u2h(q1.w);
    }

    // keep-min predicates: (i & K/2)==0; i = wc<<8 | lane<<3 | r
    const bool P1  = (lane & 1)  == 0;
    const bool P2  = (lane & 2)  == 0;
    const bool P4  = (lane & 4)  == 0;
    const bool P8  = (lane & 8)  == 0;
    const bool P16 = (lane & 16) == 0;
    const bool PW  = (wc == 0);

    // ---- Normalized bitonic sort of 512 (x2 columns via SIMD halves) ----
    IR_J1                                            // K=2
    IR_TRI4 IR_J1                                    // K=4
    IR_TRI8 IR_J2 IR_J1                              // K=8
    SHT(1,  P1)                               IR_TAIL  // K=16
    SHT(3,  P2)                    SHS(1, P1) IR_TAIL  // K=32
    SHT(7,  P4)         SHS(2, P2) SHS(1, P1) IR_TAIL  // K=64
    SHT(15, P8)  SHS(4, P4) SHS(2, P2) SHS(1, P1) IR_TAIL  // K=128
    SHT(31, P16) SHS(8, P8) SHS(4, P4) SHS(2, P2) SHS(1, P1) IR_TAIL  // K=256

    // K=512 triangle: partner i^511 -> other warp, lane^31, regs reversed.
    {
        const int sb = tid_c << 3;
        *(uint4*)(ceb + sb)     = make_uint4(h2u(v[0]),h2u(v[1]),h2u(v[2]),h2u(v[3]));
        *(uint4*)(ceb + sb + 4) = make_uint4(h2u(v[4]),h2u(v[5]),h2u(v[6]),h2u(v[7]));
        colbar(col);
        const int pb_ = (tid_c ^ 63) << 3;
        const uint4 q0 = *(const uint4*)(ceb + pb_);
        const uint4 q1 = *(const uint4*)(ceb + pb_ + 4);
        const __half2 u_[8] = { u2h(q1.w),u2h(q1.z),u2h(q1.y),u2h(q1.x),
                                u2h(q0.w),u2h(q0.z),u2h(q0.y),u2h(q0.x) };
        #pragma unroll
        for (int r_=0;r_<8;r_++) v[r_] = PW ? __hmin2(v[r_],u_[r_]) : __hmax2(v[r_],u_[r_]);
    }
    // K=512 substage j=256: partner i^256 -> other warp, same lane/regs.
    // (safe to reuse staging: partner passed event-1 colbar => initial loads done)
    {
        const int sb = tid_c << 3;
        *(uint4*)(cstg + sb)     = make_uint4(h2u(v[0]),h2u(v[1]),h2u(v[2]),h2u(v[3]));
        *(uint4*)(cstg + sb + 4) = make_uint4(h2u(v[4]),h2u(v[5]),h2u(v[6]),h2u(v[7]));
        colbar(col);
        const int pb_ = (tid_c ^ 32) << 3;
        const uint4 q0 = *(const uint4*)(cstg + pb_);
        const uint4 q1 = *(const uint4*)(cstg + pb_ + 4);
        const __half2 u_[8] = { u2h(q0.x),u2h(q0.y),u2h(q0.z),u2h(q0.w),
                                u2h(q1.x),u2h(q1.y),u2h(q1.z),u2h(q1.w) };
        #pragma unroll
        for (int r_=0;r_<8;r_++) v[r_] = PW ? __hmin2(v[r_],u_[r_]) : __hmax2(v[r_],u_[r_]);
    }
    SHS(16, P16) SHS(8, P8) SHS(4, P4) SHS(2, P2) SHS(1, P1) IR_TAIL

    // ---- Label prefix per half (exact integers in fp16, |.| <= 512) ----
    __half2 c[8];
    {
        const unsigned bits0 = h2u(v[0]);
        c[0] = u2h(0x3C003C00u | (((bits0 ^ LSB2) & LSB2) << 15));  // +/-1 per half
        #pragma unroll
        for (int r = 1; r < 8; r++) {
            const unsigned bits = h2u(v[r]);
            c[r] = __hadd2(c[r-1], u2h(0x3C003C00u | (((bits ^ LSB2) & LSB2) << 15)));
        }
    }
    __half2 incl = c[7];
    #pragma unroll
    for (int o = 1; o < 32; o <<= 1) {
        const __half2 f = u2h(__shfl_up_sync(FULL_MASK, h2u(incl), o));
        if (lane >= o) incl = __hadd2(incl, f);
    }

    if (lane == 31) ws[col][wc] = h2u(incl);
    nb[col][tid_c] = h2u(v[0]);
    if (tid_c == 63) nb[col][64] = h2u(v[7]);   // self => last gap 0 (d=0 there)
    colbar(col);

    __half2 dbase = __hsub2(incl, c[7]);
    if (wc) dbase = __hadd2(dbase, u2h(ws[col][0]));

    __half2 vn = u2h(__shfl_down_sync(FULL_MASK, h2u(v[0]), 1));
    if (lane == 31) vn = u2h(nb[col][tid_c + 1]);

    float acc = 0.0f;
    #pragma unroll
    for (int r = 0; r < 8; r++) {
        const __half2 nxt = (r < 7) ? v[r+1] : vn;
        const float2 g = __half22float2(__hsub2(nxt, v[r]));
        const float2 d = __half22float2(__hadd2(dbase, c[r]));
        acc += g.x * d.x * d.x + g.y * d.y * d.y;
    }

    // ---- Warp reduce -> CTA reduce -> device scratch fan-in ----
    #pragma unroll
    for (int o = 16; o; o >>= 1)
        acc += __shfl_xor_sync(FULL_MASK, acc, o);
    if (lane == 0) wred[(col << 1) | wc] = acc;
    __syncthreads();

    if (t == 0) {
        float s = 0.0f;
        #pragma unroll
        for (int i = 0; i < 16; i++) s += wred[i];
        atomicAdd(&g_accum[b], s * (1.0f / (float)(EN * EN)));
        __threadfence();
        const int old = atomicAdd(&g_cnt[b], 1);
        if (old == GX - 1) {
            const float tot = atomicAdd(&g_accum[b], 0.0f);  // atomic read
            out[b] = tot;
            __threadfence();
            g_accum[b] = 0.0f;   // reset for next graph replay
            g_cnt[b]   = 0;
        }
    }
}

extern "C" void kernel_launch(void* const* d_in, const int* in_sizes, int n_in,
                              void* d_out, int out_size)
{
    const float* x1 = (const float*)d_in[0];
    const float* x2 = (const float*)d_in[1];
    float* out = (float*)d_out;

    dim3 grid(GX, EB);   // (8, 16) = 128 CTAs: one wave, 16 warps/CTA
    ed_kernel<<<grid, 512>>>(x1, x2, out);
}

// round 16
// speedup vs baseline: 1.0058x; 1.0058x over previous
#include <cuda_runtime.h>
#include <cuda_fp16.h>
#include <cstdint>

// Energy distance, B=16, N=M=256, D=128. Single launch.
// fp16x2 SIMD sort: each warp sorts TWO (batch,dim) columns at once (half2
// values, HMNMX2 comparators, 32-bit shfl), 16 elems/thread, all in-warp.
// Restructure vs best-so-far: 256 CTAs x 128 thr (4 warps = 4 pair-columns)
// -> grid >= 148 (exit low-grid issue-throttle), all CTAs co-resident.
// E*N^2 = sum_k (z_{k+1}-z_k)*d_k^2, d = prefix of +/-1 labels (fp16 LSB).
// Cross-CTA fan-in via device scratch + arrival counter (16 CTAs/batch).

#define EB 16
#define EN 256
#define ED 128
#define GXB 16          // CTAs per batch (grid.x)
#define CSTRIDE 648     // 32-bit words per pair-column (phys max 635)
#define FULL_MASK 0xFFFFFFFFu
#define LSB2 0x00010001u

__device__ float g_accum[EB];   // zero-init; reset by last CTA each run
__device__ int   g_cnt[EB];

__device__ __forceinline__ unsigned h2u(__half2 h){ union{__half2 h; unsigned u;} x; x.h=h; return x.u; }
__device__ __forceinline__ __half2 u2h(unsigned u){ union{__half2 h; unsigned u;} x; x.u=u; return x.h; }

// Packed ascending compare-exchange (both halves independently).
#define CEP(a,b) { const __half2 lo_=__hmin2((a),(b)), hi_=__hmax2((a),(b)); (a)=lo_; (b)=hi_; }

#define IR_J1 { CEP(v[0],v[1]) CEP(v[2],v[3]) CEP(v[4],v[5]) CEP(v[6],v[7]) \
                CEP(v[8],v[9]) CEP(v[10],v[11]) CEP(v[12],v[13]) CEP(v[14],v[15]) }
#define IR_J2 { CEP(v[0],v[2]) CEP(v[1],v[3]) CEP(v[4],v[6]) CEP(v[5],v[7]) \
                CEP(v[8],v[10]) CEP(v[9],v[11]) CEP(v[12],v[14]) CEP(v[13],v[15]) }
#define IR_J4 { CEP(v[0],v[4]) CEP(v[1],v[5]) CEP(v[2],v[6]) CEP(v[3],v[7]) \
                CEP(v[8],v[12]) CEP(v[9],v[13]) CEP(v[10],v[14]) CEP(v[11],v[15]) }
#define IR_J8 { CEP(v[0],v[8]) CEP(v[1],v[9]) CEP(v[2],v[10]) CEP(v[3],v[11]) \
                CEP(v[4],v[12]) CEP(v[5],v[13]) CEP(v[6],v[14]) CEP(v[7],v[15]) }
#define IR_TRI4  { CEP(v[0],v[3]) CEP(v[1],v[2]) CEP(v[4],v[7]) CEP(v[5],v[6]) \
                   CEP(v[8],v[11]) CEP(v[9],v[10]) CEP(v[12],v[15]) CEP(v[13],v[14]) }
#define IR_TRI8  { CEP(v[0],v[7]) CEP(v[1],v[6]) CEP(v[2],v[5]) CEP(v[3],v[4]) \
                   CEP(v[8],v[15]) CEP(v[9],v[14]) CEP(v[10],v[13]) CEP(v[11],v[12]) }
#define IR_TRI16 { CEP(v[0],v[15]) CEP(v[1],v[14]) CEP(v[2],v[13]) CEP(v[3],v[12]) \
                   CEP(v[4],v[11]) CEP(v[5],v[10]) CEP(v[6],v[9]) CEP(v[7],v[8]) }
#define IR_TAIL { IR_J8 IR_J4 IR_J2 IR_J1 }

// Cross-lane substage via shfl: partner lane^m, same register index.
#define SHS(m, P) { __half2 u_[16]; \
    _Pragma("unroll") for (int r_=0;r_<16;r_++) \
        u_[r_] = u2h(__shfl_xor_sync(FULL_MASK, h2u(v[r_]), (m))); \
    _Pragma("unroll") for (int r_=0;r_<16;r_++) \
        v[r_] = (P) ? __hmin2(v[r_],u_[r_]) : __hmax2(v[r_],u_[r_]); }

// Cross-lane triangle via shfl: partner lane^m, register index reversed.
#define SHT(m, P) { __half2 u_[16]; \
    _Pragma("unroll") for (int r_=0;r_<16;r_++) \
        u_[r_] = u2h(__shfl_xor_sync(FULL_MASK, h2u(v[15-r_]), (m))); \
    _Pragma("unroll") for (int r_=0;r_<16;r_++) \
        v[r_] = (P) ? __hmin2(v[r_],u_[r_]) : __hmax2(v[r_],u_[r_]); }

__global__ __launch_bounds__(128) void ed_kernel(
    const float* __restrict__ x1,
    const float* __restrict__ x2,
    float* __restrict__ out)
{
    __shared__ __align__(16) unsigned stg[4 * CSTRIDE];   // 10.4 KB
    __shared__ float wred[4];

    const int b  = blockIdx.y;
    const int d0 = blockIdx.x << 3;        // 8 dims per CTA = 4 half2 pairs
    const int t  = threadIdx.x;            // 0..127
    const int lane = t & 31;
    const int w    = t >> 5;               // warp == pair-column 0..3

    // ---- Stage: each thread handles 2 samples (t, t+128), 8 dims of both
    //      inputs, packing dim pairs into half2. Labels: x1->LSB|1, x2->&~1.
    //      Element i = 16*L + r of pair p lives at word 20*L + r; x1 at i=s,
    //      x2 at i=256+s (word offset +320).
    #pragma unroll
    for (int k = 0; k < 2; k++) {
        const int s = t + (k << 7);
        const size_t off = ((size_t)(b * EN + s)) * ED + d0;
        const float4 a0 = *(const float4*)(x1 + off);
        const float4 a1 = *(const float4*)(x1 + off + 4);
        const float4 b0 = *(const float4*)(x2 + off);
        const float4 b1 = *(const float4*)(x2 + off + 4);
        const unsigned pa[4] = {
            h2u(__floats2half2_rn(a0.x, a0.y)) | LSB2,
            h2u(__floats2half2_rn(a0.z, a0.w)) | LSB2,
            h2u(__floats2half2_rn(a1.x, a1.y)) | LSB2,
            h2u(__floats2half2_rn(a1.z, a1.w)) | LSB2 };
        const unsigned pb[4] = {
            h2u(__floats2half2_rn(b0.x, b0.y)) & ~LSB2,
            h2u(__floats2half2_rn(b0.z, b0.w)) & ~LSB2,
            h2u(__floats2half2_rn(b1.x, b1.y)) & ~LSB2,
            h2u(__floats2half2_rn(b1.z, b1.w)) & ~LSB2 };
        const int pt = s + ((s >> 4) << 2);          // phys(s)
        #pragma unroll
        for (int c = 0; c < 4; c++) {
            unsigned* cb = stg + c * CSTRIDE;
            cb[pt]       = pa[c];
            cb[pt + 320] = pb[c];
        }
    }
    __syncthreads();

    const unsigned* buf = stg + w * CSTRIDE;
    const int base = 20 * lane;

    __half2 v[16];
    {
        const uint4 q0=*(const uint4*)(buf+base),   q1=*(const uint4*)(buf+base+4);
        const uint4 q2=*(const uint4*)(buf+base+8), q3=*(const uint4*)(buf+base+12);
        v[0]=u2h(q0.x); v[1]=u2h(q0.y); v[2]=u2h(q0.z); v[3]=u2h(q0.w);
        v[4]=u2h(q1.x); v[5]=u2h(q1.y); v[6]=u2h(q1.z); v[7]=u2h(q1.w);
        v[8]=u2h(q2.x); v[9]=u2h(q2.y); v[10]=u2h(q2.z); v[11]=u2h(q2.w);
        v[12]=u2h(q3.x); v[13]=u2h(q3.y); v[14]=u2h(q3.z); v[15]=u2h(q3.w);
    }

    const bool P1  = (lane & 1)  == 0;
    const bool P2  = (lane & 2)  == 0;
    const bool P4  = (lane & 4)  == 0;
    const bool P8  = (lane & 8)  == 0;
    const bool P16 = (lane & 16) == 0;

    // ---- Normalized bitonic sort of 512 (x2 columns), all in-warp ----
    IR_J1                                        // K=2
    IR_TRI4  IR_J1                               // K=4
    IR_TRI8  IR_J2 IR_J1                         // K=8
    IR_TRI16 IR_J4 IR_J2 IR_J1                   // K=16
    SHT(1,  P1)                                       IR_TAIL  // K=32
    SHT(3,  P2)                            SHS(1, P1) IR_TAIL  // K=64
    SHT(7,  P4)                 SHS(2, P2) SHS(1, P1) IR_TAIL  // K=128
    SHT(15, P8)      SHS(4, P4) SHS(2, P2) SHS(1, P1) IR_TAIL  // K=256
    SHT(31, P16) SHS(8, P8) SHS(4, P4) SHS(2, P2) SHS(1, P1) IR_TAIL  // K=512

    // ---- Label prefix per half (exact integers in fp16, |.| <= 512) ----
    __half2 c[16];
    {
        const unsigned bits0 = h2u(v[0]);
        c[0] = u2h(0x3C003C00u | (((bits0 ^ LSB2) & LSB2) << 15));  // +/-1 per half
        #pragma unroll
        for (int r = 1; r < 16; r++) {
            const unsigned bits = h2u(v[r]);
            const __half2 pm1 = u2h(0x3C003C00u | (((bits ^ LSB2) & LSB2) << 15));
            c[r] = __hadd2(c[r-1], pm1);
        }
    }

    __half2 incl = c[15];
    #pragma unroll
    for (int o = 1; o < 32; o <<= 1) {
        const __half2 f = u2h(__shfl_up_sync(FULL_MASK, h2u(incl), o));
        if (lane >= o) incl = __hadd2(incl, f);
    }
    const __half2 dbase = __hsub2(incl, c[15]);

    // Neighbor for the r=15 gap; lane 31's d is 0 in both halves (labels sum
    // to 0), so its (self) shfl value contributes exactly 0.
    const __half2 vn = u2h(__shfl_down_sync(FULL_MASK, h2u(v[0]), 1));

    float acc = 0.0f;
    #pragma unroll
    for (int r = 0; r < 16; r++) {
        const __half2 nxt = (r < 15) ? v[r+1] : vn;
        const float2 g = __half22float2(__hsub2(nxt, v[r]));
        const float2 d = __half22float2(__hadd2(dbase, c[r]));
        acc += g.x * d.x * d.x + g.y * d.y * d.y;
    }

    // ---- Warp reduce -> CTA reduce -> device scratch fan-in ----
    #pragma unroll
    for (int o = 16; o; o >>= 1)
        acc += __shfl_xor_sync(FULL_MASK, acc, o);
    if (lane == 0) wred[w] = acc;
    __syncthreads();

    if (t == 0) {
        const float s = wred[0] + wred[1] + wred[2] + wred[3];
        atomicAdd(&g_accum[b], s * (1.0f / (float)(EN * EN)));
        __threadfence();
        const int old = atomicAdd(&g_cnt[b], 1);
        if (old == GXB - 1) {
            const float tot = atomicAdd(&g_accum[b], 0.0f);  // atomic read
            out[b] = tot;
            __threadfence();
            g_accum[b] = 0.0f;   // reset for next graph replay
            g_cnt[b]   = 0;
        }
    }
}

extern "C" void kernel_launch(void* const* d_in, const int* in_sizes, int n_in,
                              void* d_out, int out_size)
{
    const float* x1 = (const float*)d_in[0];
    const float* x2 = (const float*)d_in[1];
    float* out = (float*)d_out;

    dim3 grid(GXB, EB);   // (16, 16) = 256 CTAs >= 148: all co-resident
    ed_kernel<<<grid, 128>>>(x1, x2, out);
}